// round 4
// baseline (speedup 1.0000x reference)
#include <cuda_runtime.h>
#include <cuda_bf16.h>
#include <cstdint>

#define BB 16
#define CC 128
#define HH 56
#define WWI 56
#define TOK (BB*HH*WWI)          // 50176
#define QKC 128
#define QKVC 384
#define NWIN 7
#define WHS 8
#define P2 49
#define W2 64
#define TOPK 4
#define HEADS 4
#define HD 32
#define SCALE 0.08838834764831845f

typedef unsigned long long ull;

// ---------------- scratch (device globals; no allocation) ----------------
__device__ float g_xh [TOK*CC];
__device__ float g_qkv[TOK*QKVC];
__device__ float g_att[TOK*CC];
__device__ float g_qwin[BB*P2*CC];
__device__ float g_kwin[BB*P2*CC];
__device__ int   g_idx [BB*P2*TOPK];
// split-bf16 activations
__device__ __nv_bfloat16 g_yh [TOK*CC],  g_yl [TOK*CC];
__device__ __nv_bfloat16 g_ath[TOK*CC],  g_atl[TOK*CC];
__device__ __nv_bfloat16 g_h1h[TOK*3*CC],g_h1l[TOK*3*CC];
// split-bf16 weights, transposed to [N,K]
__device__ __nv_bfloat16 g_wqh[QKVC*CC], g_wql[QKVC*CC];
__device__ __nv_bfloat16 g_woh[CC*CC],   g_wol[CC*CC];
__device__ __nv_bfloat16 g_w1h[3*CC*CC], g_w1l[3*CC*CC];
__device__ __nv_bfloat16 g_w2h[CC*3*CC], g_w2l[CC*3*CC];

// ---------------- helpers ----------------
__device__ __forceinline__ uint32_t smem_u32(const void* p){
    uint32_t a;
    asm("{ .reg .u64 t; cvta.to.shared.u64 t, %1; cvt.u32.u64 %0, t; }" : "=r"(a) : "l"(p));
    return a;
}
__device__ __forceinline__ void ldm_x4(uint32_t& r0,uint32_t& r1,uint32_t& r2,uint32_t& r3, uint32_t addr){
    asm volatile("ldmatrix.sync.aligned.m8n8.x4.shared.b16 {%0,%1,%2,%3}, [%4];"
        : "=r"(r0),"=r"(r1),"=r"(r2),"=r"(r3) : "r"(addr));
}
__device__ __forceinline__ void mma_bf16(float* d, const uint32_t* a, const uint32_t* b){
    asm volatile("mma.sync.aligned.m16n8k16.row.col.f32.bf16.bf16.f32 "
        "{%0,%1,%2,%3}, {%4,%5,%6,%7}, {%8,%9}, {%0,%1,%2,%3};"
        : "+f"(d[0]),"+f"(d[1]),"+f"(d[2]),"+f"(d[3])
        : "r"(a[0]),"r"(a[1]),"r"(a[2]),"r"(a[3]), "r"(b[0]),"r"(b[1]));
}
__device__ __forceinline__ ull pack2(float lo, float hi){
    ull r; asm("mov.b64 %0, {%1,%2};" : "=l"(r) : "f"(lo), "f"(hi)); return r;
}
__device__ __forceinline__ void unpack2(ull v, float& lo, float& hi){
    asm("mov.b64 {%0,%1}, %2;" : "=f"(lo), "=f"(hi) : "l"(v));
}
__device__ __forceinline__ void fma2(ull &c, ull a, ull b){
    asm("fma.rn.f32x2 %0, %1, %2, %0;" : "+l"(c) : "l"(a), "l"(b));
}
__device__ __forceinline__ void mul2(ull &a, ull b){
    asm("mul.rn.f32x2 %0, %0, %1;" : "+l"(a) : "l"(b));
}
__device__ __forceinline__ float gelu_exact(float v){
    return 0.5f * v * (1.0f + erff(v * 0.70710678118654752f));
}
__device__ __forceinline__ void split_bf16(float v, __nv_bfloat16& h, __nv_bfloat16& l){
    h = __float2bfloat16(v);
    l = __float2bfloat16(v - __bfloat162float(h));
}

// ---------------- fused weight transpose + split (one launch) ----------------
__global__ __launch_bounds__(256) void k_wsplit_all(
    const float* __restrict__ qkv_w, const float* __restrict__ wo_w,
    const float* __restrict__ mlp_w1, const float* __restrict__ mlp_w2,
    __nv_bfloat16* __restrict__ wqh, __nv_bfloat16* __restrict__ wql,
    __nv_bfloat16* __restrict__ woh, __nv_bfloat16* __restrict__ wol,
    __nv_bfloat16* __restrict__ w1h, __nv_bfloat16* __restrict__ w1l,
    __nv_bfloat16* __restrict__ w2h, __nv_bfloat16* __restrict__ w2l)
{
    int blk = blockIdx.x;
    const float* src; __nv_bfloat16 *dh, *dl; int K, N, base;
    if (blk < 192)      { src = qkv_w;  dh = wqh; dl = wql; K = CC;   N = QKVC; base = 0;   }
    else if (blk < 256) { src = wo_w;   dh = woh; dl = wol; K = CC;   N = CC;   base = 192; }
    else if (blk < 448) { src = mlp_w1; dh = w1h; dl = w1l; K = CC;   N = 3*CC; base = 256; }
    else                { src = mlp_w2; dh = w2h; dl = w2l; K = 3*CC; N = CC;   base = 448; }
    int i = (blk - base) * 256 + threadIdx.x;
    if (i >= N * K) return;
    int n = i / K, k = i - n * K;
    float v = src[(size_t)k * N + n];
    __nv_bfloat16 h, l; split_bf16(v, h, l);
    dh[i] = h; dl[i] = l;
}

// ---------------- kernel 1: x + dwconv3x3(x) -> xh (NHWC) ----------------
__global__ __launch_bounds__(256) void k_posconv(const float* __restrict__ x,
                                                 const float* __restrict__ pw,
                                                 const float* __restrict__ pb,
                                                 float* __restrict__ xh){
    __shared__ __align__(16) float s[3*64*57];
    int bh = blockIdx.x; int b = bh / HH, h = bh % HH;
    int c0 = blockIdx.y * 64;
    int tid = threadIdx.x;
    for (int l = tid; l < 3*64*56; l += 256){
        int row = l / (64*56);
        int rem = l - row*(64*56);
        int c   = rem / 56;
        int wv  = rem - c*56;
        int hr  = h + row - 1;
        float v = 0.f;
        if (hr >= 0 && hr < HH)
            v = x[((size_t)((b*CC + c0 + c)*HH + hr))*WWI + wv];
        s[row*64*57 + c*57 + wv] = v;
    }
    __syncthreads();
    int c = tid & 63;
    float wgt[9];
    #pragma unroll
    for (int t = 0; t < 9; t++) wgt[t] = pw[(c0 + c)*9 + t];
    float bias = pb[c0 + c];
    for (int l = tid; l < 56*64; l += 256){
        int w = l >> 6;
        float acc = bias;
        #pragma unroll
        for (int ky = 0; ky < 3; ky++){
            const float* srow = &s[ky*64*57 + c*57];
            #pragma unroll
            for (int kx = 0; kx < 3; kx++){
                int ww = w + kx - 1;
                if (ww >= 0 && ww < WWI) acc += wgt[ky*3+kx] * srow[ww];
            }
        }
        acc += s[1*64*57 + c*57 + w];   // residual (center x)
        xh[((size_t)((b*HH + h)*WWI + w))*CC + c0 + c] = acc;
    }
}

// ---------------- kernel 2: LayerNorm over C -> split bf16 ----------------
__global__ __launch_bounds__(256) void k_ln(const float* __restrict__ in,
                                            const float* __restrict__ g,
                                            const float* __restrict__ bt,
                                            __nv_bfloat16* __restrict__ oh,
                                            __nv_bfloat16* __restrict__ ol){
    int warp = threadIdx.x >> 5, lane = threadIdx.x & 31;
    int tok = blockIdx.x * 8 + warp;
    const float4* ip = (const float4*)(in + (size_t)tok * CC);
    float4 v = ip[lane];
    float s = v.x + v.y + v.z + v.w;
    float q = v.x*v.x + v.y*v.y + v.z*v.z + v.w*v.w;
    #pragma unroll
    for (int o = 16; o; o >>= 1){
        s += __shfl_xor_sync(0xffffffffu, s, o);
        q += __shfl_xor_sync(0xffffffffu, q, o);
    }
    float m   = s * (1.f/128.f);
    float var = q * (1.f/128.f) - m*m;
    float r   = rsqrtf(var + 1e-6f);
    float4 gg = ((const float4*)g)[lane];
    float4 bb = ((const float4*)bt)[lane];
    float o0 = (v.x - m)*r*gg.x + bb.x;
    float o1 = (v.y - m)*r*gg.y + bb.y;
    float o2 = (v.z - m)*r*gg.z + bb.z;
    float o3 = (v.w - m)*r*gg.w + bb.w;
    __nv_bfloat16 h0,h1,h2,h3,l0,l1,l2,l3;
    split_bf16(o0,h0,l0); split_bf16(o1,h1,l1); split_bf16(o2,h2,l2); split_bf16(o3,h3,l3);
    size_t off = (size_t)tok * CC + lane*4;
    *(__nv_bfloat162*)(oh + off)     = __nv_bfloat162(h0, h1);
    *(__nv_bfloat162*)(oh + off + 2) = __nv_bfloat162(h2, h3);
    *(__nv_bfloat162*)(ol + off)     = __nv_bfloat162(l0, l1);
    *(__nv_bfloat162*)(ol + off + 2) = __nv_bfloat162(l2, l3);
}

// ---------------- HMMA GEMM: C[M,N] = A[M,K] @ W, split-bf16 ----------------
// A: hi/lo bf16 [M,K] row-major. B: hi/lo bf16 [N,K] row-major (= col-major KxN operand).
// TERMS: 3 = Ah*Bh + Al*Bh + Ah*Bl ; 2 = Ah*Bh + Al*Bh (B lo dropped entirely)
// EPI: 0 = bias -> fp32 C ; 1 = bias+GELU -> split bf16 (C1,C2) ; 2 = bias+residual R -> fp32 C
#define ASTR 72   // smem row stride in bf16 (144B: conflict-free ldmatrix)
template<int EPI, int TERMS>
__global__ __launch_bounds__(256) void k_mma_gemm(
    const __nv_bfloat16* __restrict__ Ah, const __nv_bfloat16* __restrict__ Al,
    const __nv_bfloat16* __restrict__ Bh, const __nv_bfloat16* __restrict__ Bl,
    const float* __restrict__ bias, const float* __restrict__ R,
    float* __restrict__ C, __nv_bfloat16* __restrict__ C1, __nv_bfloat16* __restrict__ C2,
    int N, int K)
{
    extern __shared__ __align__(16) __nv_bfloat16 sm[];
    __nv_bfloat16* sAh = sm;                    // 128 x ASTR
    __nv_bfloat16* sAl = sm + 128*ASTR;         // 128 x ASTR
    __nv_bfloat16* sBh = sm + 2*128*ASTR;       // 64 x ASTR
    __nv_bfloat16* sBl = sm + 2*128*ASTR + 64*ASTR;

    int tid = threadIdx.x;
    int warp = tid >> 5, lane = tid & 31;
    int wy = warp >> 1, wx = warp & 1;          // wy: M (0..3), wx: N (0..1)
    int bm = blockIdx.x * 128, bn = blockIdx.y * 64;

    float d[2][4][4];
    #pragma unroll
    for (int mt = 0; mt < 2; mt++)
        #pragma unroll
        for (int nt = 0; nt < 4; nt++)
            #pragma unroll
            for (int i = 0; i < 4; i++) d[mt][nt][i] = 0.f;

    int lr = tid >> 3;          // 0..31
    int lc = (tid & 7) * 8;     // 0..56

    for (int kc = 0; kc < K; kc += 64){
        if (kc) __syncthreads();
        #pragma unroll
        for (int p = 0; p < 4; p++){
            int row = p*32 + lr;
            *(uint4*)&sAh[row*ASTR + lc] = *(const uint4*)(Ah + (size_t)(bm+row)*K + kc + lc);
            *(uint4*)&sAl[row*ASTR + lc] = *(const uint4*)(Al + (size_t)(bm+row)*K + kc + lc);
        }
        #pragma unroll
        for (int p = 0; p < 2; p++){
            int row = p*32 + lr;
            *(uint4*)&sBh[row*ASTR + lc] = *(const uint4*)(Bh + (size_t)(bn+row)*K + kc + lc);
            if (TERMS == 3)
                *(uint4*)&sBl[row*ASTR + lc] = *(const uint4*)(Bl + (size_t)(bn+row)*K + kc + lc);
        }
        __syncthreads();
        #pragma unroll
        for (int ks = 0; ks < 4; ks++){
            uint32_t ah[2][4], al[2][4], bh[4][2], bl[4][2];
            #pragma unroll
            for (int mt = 0; mt < 2; mt++){
                int r = wy*32 + mt*16 + (lane & 15);
                int c = ks*16 + (lane >> 4)*8;
                ldm_x4(ah[mt][0],ah[mt][1],ah[mt][2],ah[mt][3], smem_u32(&sAh[r*ASTR + c]));
                ldm_x4(al[mt][0],al[mt][1],al[mt][2],al[mt][3], smem_u32(&sAl[r*ASTR + c]));
            }
            #pragma unroll
            for (int nn = 0; nn < 2; nn++){
                int g8 = lane >> 3;
                int n = wx*32 + nn*16 + ((g8 >> 1) ? 8 : 0) + (lane & 7);
                int c = ks*16 + (g8 & 1)*8;
                uint32_t r0,r1,r2,r3;
                ldm_x4(r0,r1,r2,r3, smem_u32(&sBh[n*ASTR + c]));
                bh[nn*2+0][0]=r0; bh[nn*2+0][1]=r1; bh[nn*2+1][0]=r2; bh[nn*2+1][1]=r3;
                if (TERMS == 3){
                    ldm_x4(r0,r1,r2,r3, smem_u32(&sBl[n*ASTR + c]));
                    bl[nn*2+0][0]=r0; bl[nn*2+0][1]=r1; bl[nn*2+1][0]=r2; bl[nn*2+1][1]=r3;
                }
            }
            #pragma unroll
            for (int mt = 0; mt < 2; mt++)
                #pragma unroll
                for (int nt = 0; nt < 4; nt++){
                    mma_bf16(d[mt][nt], ah[mt], bh[nt]);       // Ah*Bh
                    mma_bf16(d[mt][nt], al[mt], bh[nt]);       // Al*Bh
                    if (TERMS == 3)
                        mma_bf16(d[mt][nt], ah[mt], bl[nt]);   // Ah*Bl
                }
        }
    }

    // epilogue: c0,c1 -> row g cols 2t,2t+1 ; c2,c3 -> row g+8
    int g = lane >> 2, t = lane & 3;
    #pragma unroll
    for (int mt = 0; mt < 2; mt++){
        #pragma unroll
        for (int nt = 0; nt < 4; nt++){
            int c = bn + wx*32 + nt*8 + t*2;
            float b0 = bias[c], b1 = bias[c+1];
            #pragma unroll
            for (int hr = 0; hr < 2; hr++){
                int r = bm + wy*32 + mt*16 + g + hr*8;
                float v0 = d[mt][nt][hr*2+0] + b0;
                float v1 = d[mt][nt][hr*2+1] + b1;
                size_t go = (size_t)r * N + c;
                if (EPI == 0){
                    float2 o; o.x = v0; o.y = v1;
                    *(float2*)(C + go) = o;
                } else if (EPI == 1){
                    v0 = gelu_exact(v0); v1 = gelu_exact(v1);
                    __nv_bfloat16 h0,h1,l0,l1;
                    split_bf16(v0,h0,l0); split_bf16(v1,h1,l1);
                    *(__nv_bfloat162*)(C1 + go) = __nv_bfloat162(h0, h1);
                    *(__nv_bfloat162*)(C2 + go) = __nv_bfloat162(l0, l1);
                } else {
                    float2 rr = *(const float2*)(R + go);
                    float2 o; o.x = v0 + rr.x; o.y = v1 + rr.y;
                    *(float2*)(C + go) = o;
                }
            }
        }
    }
}
#define GEMM_SMEM ((2*128*ASTR + 2*64*ASTR) * 2)

// ---------------- kernel 4: window means of q and k (256 thr) ----------------
__global__ __launch_bounds__(256) void k_winmean(const float* __restrict__ qkv,
                                                 float* __restrict__ qwin,
                                                 float* __restrict__ kwin){
    int bp = blockIdx.x; int b = bp / P2, p = bp - b*P2;
    int tid = threadIdx.x;
    int c = tid & 127, isK = tid >> 7;
    int hb = (p / NWIN) * WHS, wb = (p % NWIN) * WHS;
    const float* src = qkv + (isK ? QKC : 0) + c;
    float s = 0.f;
    #pragma unroll 8
    for (int r = 0; r < W2; r++){
        size_t tok = (size_t)(b*HH + hb + (r >> 3))*WWI + wb + (r & 7);
        s += src[tok*QKVC];
    }
    (isK ? kwin : qwin)[(size_t)bp*CC + c] = s * (1.f/64.f);
}

// ---------------- kernel 5: routing logits + top-4 ----------------
__global__ __launch_bounds__(64) void k_route(const float* __restrict__ qwin,
                                              const float* __restrict__ kwin,
                                              int* __restrict__ idx){
    __shared__ float qr[128];
    __shared__ float lg[49];
    int bp = blockIdx.x; int b = bp / P2;
    int t = threadIdx.x;
    qr[t]      = qwin[(size_t)bp*CC + t];
    qr[t + 64] = qwin[(size_t)bp*CC + 64 + t];
    __syncthreads();
    if (t < P2){
        const float* kr = kwin + (size_t)(b*P2 + t)*CC;
        float s = 0.f;
        #pragma unroll 8
        for (int c = 0; c < CC; c++) s += qr[c] * kr[c];
        lg[t] = s;
    }
    __syncthreads();
    if (t == 0){
        unsigned long long used = 0ull;
        for (int r = 0; r < TOPK; r++){
            float best = -1e30f; int bi = 0;
            for (int j = 0; j < P2; j++)
                if (!((used >> j) & 1ull) && lg[j] > best){ best = lg[j]; bi = j; }
            used |= 1ull << bi;
            idx[bp*TOPK + r] = bi;
        }
    }
}

// ---------------- kernel 6: gathered window attention (f32x2 online softmax) ----------------
__global__ __launch_bounds__(256) void k_attn(const float* __restrict__ qkv,
                                              const int* __restrict__ idx,
                                              float* __restrict__ op){
    extern __shared__ __align__(16) float kv[];   // [0..8191]=K chunk, [8192..16383]=V chunk
    int bp = blockIdx.x; int b = bp / P2, p = bp - b*P2;
    int tid = threadIdx.x;
    int h = tid >> 6, r = tid & 63;
    int hq = (p / NWIN)*WHS + (r >> 3);
    int wq = (p % NWIN)*WHS + (r & 7);
    const float* qp = qkv + ((size_t)((b*HH + hq)*WWI + wq))*QKVC + h*HD;
    ull q2[16], o2[16];
    #pragma unroll
    for (int j = 0; j < 16; j++){
        q2[j] = pack2(qp[2*j] * SCALE, qp[2*j+1] * SCALE);
        o2[j] = 0ull;
    }
    float m = -1e30f, l = 0.f;

    for (int t = 0; t < TOPK; t++){
        int wsel = idx[bp*TOPK + t];
        int bh2 = (wsel / NWIN)*WHS, bw2 = (wsel % NWIN)*WHS;
        __syncthreads();
        #pragma unroll 4
        for (int i = 0; i < 64; i++){
            int li = i*256 + tid;
            int k = li >> 8;
            int c = li & 255;
            size_t tk = (size_t)(b*HH + bh2 + (k >> 3))*WWI + bw2 + (k & 7);
            kv[((c >> 7) << 13) + k*128 + (c & 127)] = qkv[tk*QKVC + QKC + c];
        }
        __syncthreads();
        #pragma unroll 1
        for (int sub = 0; sub < 4; sub++){
            float s16[16];
            const float* Kb = &kv[(sub*16)*128 + h*HD];
            #pragma unroll
            for (int k = 0; k < 16; k++){
                const ull* kr = (const ull*)(Kb + k*128);
                ull acc = 0ull;
                #pragma unroll
                for (int j = 0; j < 16; j++) fma2(acc, kr[j], q2[j]);
                float lo, hi; unpack2(acc, lo, hi);
                s16[k] = lo + hi;
            }
            float mc = s16[0];
            #pragma unroll
            for (int k = 1; k < 16; k++) mc = fmaxf(mc, s16[k]);
            float mn = fmaxf(m, mc);
            float corr = __expf(m - mn);
            m = mn;
            l *= corr;
            ull corr2 = pack2(corr, corr);
            #pragma unroll
            for (int j = 0; j < 16; j++) mul2(o2[j], corr2);
            const float* Vb = &kv[8192 + (sub*16)*128 + h*HD];
            #pragma unroll
            for (int k = 0; k < 16; k++){
                float pe = __expf(s16[k] - mn);
                l += pe;
                ull pe2 = pack2(pe, pe);
                const ull* vr = (const ull*)(Vb + k*128);
                #pragma unroll
                for (int j = 0; j < 16; j++) fma2(o2[j], vr[j], pe2);
            }
        }
    }
    float inv = 1.f / l;
    float* outp = op + ((size_t)((b*HH + hq)*WWI + wq))*CC + h*HD;
    #pragma unroll
    for (int j = 0; j < 16; j++){
        float lo, hi; unpack2(o2[j], lo, hi);
        outp[2*j]   = lo * inv;
        outp[2*j+1] = hi * inv;
    }
}

// ---------------- kernel 7: LEPE 5x5 dwconv on v, add att, write split bf16 ----------------
__global__ __launch_bounds__(256) void k_lepe(const float* __restrict__ qkv,
                                              const float* __restrict__ lw,
                                              const float* __restrict__ lb,
                                              const float* __restrict__ att,
                                              __nv_bfloat16* __restrict__ oh,
                                              __nv_bfloat16* __restrict__ ol){
    __shared__ __align__(16) float s[5*32*57];
    int bh = blockIdx.x; int b = bh / HH, h = bh % HH;
    int c0 = blockIdx.y * 32;
    int tid = threadIdx.x;
    for (int l = tid; l < 5*32*56; l += 256){
        int row = l / (32*56);
        int rem = l - row*(32*56);
        int wv  = rem >> 5;
        int c   = rem & 31;
        int hr  = h + row - 2;
        float v = 0.f;
        if (hr >= 0 && hr < HH)
            v = qkv[((size_t)((b*HH + hr)*WWI + wv))*QKVC + 2*QKC + c0 + c];
        s[row*32*57 + c*57 + wv] = v;
    }
    __syncthreads();
    int c = tid & 31;
    float wg[25];
    #pragma unroll
    for (int t = 0; t < 25; t++) wg[t] = lw[(c0 + c)*25 + t];
    float bias = lb[c0 + c];
    for (int l = tid; l < 56*32; l += 256){
        int w = l >> 5;
        float acc = bias;
        #pragma unroll
        for (int ky = 0; ky < 5; ky++){
            const float* srow = &s[ky*32*57 + c*57];
            #pragma unroll
            for (int kx = 0; kx < 5; kx++){
                int ww = w + kx - 2;
                if (ww >= 0 && ww < WWI) acc += wg[ky*5+kx] * srow[ww];
            }
        }
        size_t go = ((size_t)((b*HH + h)*WWI + w))*CC + c0 + c;
        float v = att[go] + acc;
        __nv_bfloat16 hh, ll; split_bf16(v, hh, ll);
        oh[go] = hh; ol[go] = ll;
    }
}

// ---------------- kernel 8: NHWC -> NCHW ----------------
__global__ void k_tr(const float* __restrict__ in, float* __restrict__ out){
    __shared__ float t[32][33];
    int b = blockIdx.z, c0 = blockIdx.y*32, p0 = blockIdx.x*32;
    int tx = threadIdx.x, ty = threadIdx.y;
    #pragma unroll
    for (int u = 0; u < 4; u++)
        t[ty + u*8][tx] = in[((size_t)(b*(HH*WWI) + p0 + ty + u*8))*CC + c0 + tx];
    __syncthreads();
    #pragma unroll
    for (int u = 0; u < 4; u++)
        out[((size_t)(b*CC + c0 + ty + u*8))*(HH*WWI) + p0 + tx] = t[tx][ty + u*8];
}

// ---------------- launcher ----------------
extern "C" void kernel_launch(void* const* d_in, const int* in_sizes, int n_in,
                              void* d_out, int out_size){
    const float* x      = (const float*)d_in[0];
    const float* pos_w  = (const float*)d_in[1];
    const float* pos_b  = (const float*)d_in[2];
    const float* ln1_g  = (const float*)d_in[3];
    const float* ln1_b  = (const float*)d_in[4];
    const float* qkv_w  = (const float*)d_in[5];
    const float* qkv_b  = (const float*)d_in[6];
    const float* lepe_w = (const float*)d_in[7];
    const float* lepe_b = (const float*)d_in[8];
    const float* wo_w   = (const float*)d_in[9];
    const float* wo_b   = (const float*)d_in[10];
    const float* ln2_g  = (const float*)d_in[11];
    const float* ln2_b  = (const float*)d_in[12];
    const float* mlp_w1 = (const float*)d_in[13];
    const float* mlp_b1 = (const float*)d_in[14];
    const float* mlp_w2 = (const float*)d_in[15];
    const float* mlp_b2 = (const float*)d_in[16];
    float* out = (float*)d_out;

    float *p_xh, *p_qkv, *p_att, *p_qwin, *p_kwin;
    int *p_idx;
    __nv_bfloat16 *p_yh, *p_yl, *p_ath, *p_atl, *p_h1h, *p_h1l;
    __nv_bfloat16 *p_wqh, *p_wql, *p_woh, *p_wol, *p_w1h, *p_w1l, *p_w2h, *p_w2l;
    cudaGetSymbolAddress((void**)&p_xh,  g_xh);
    cudaGetSymbolAddress((void**)&p_qkv, g_qkv);
    cudaGetSymbolAddress((void**)&p_att, g_att);
    cudaGetSymbolAddress((void**)&p_qwin,g_qwin);
    cudaGetSymbolAddress((void**)&p_kwin,g_kwin);
    cudaGetSymbolAddress((void**)&p_idx, g_idx);
    cudaGetSymbolAddress((void**)&p_yh,  g_yh);
    cudaGetSymbolAddress((void**)&p_yl,  g_yl);
    cudaGetSymbolAddress((void**)&p_ath, g_ath);
    cudaGetSymbolAddress((void**)&p_atl, g_atl);
    cudaGetSymbolAddress((void**)&p_h1h, g_h1h);
    cudaGetSymbolAddress((void**)&p_h1l, g_h1l);
    cudaGetSymbolAddress((void**)&p_wqh, g_wqh);
    cudaGetSymbolAddress((void**)&p_wql, g_wql);
    cudaGetSymbolAddress((void**)&p_woh, g_woh);
    cudaGetSymbolAddress((void**)&p_wol, g_wol);
    cudaGetSymbolAddress((void**)&p_w1h, g_w1h);
    cudaGetSymbolAddress((void**)&p_w1l, g_w1l);
    cudaGetSymbolAddress((void**)&p_w2h, g_w2h);
    cudaGetSymbolAddress((void**)&p_w2l, g_w2l);

    cudaFuncSetAttribute(k_mma_gemm<0,3>, cudaFuncAttributeMaxDynamicSharedMemorySize, GEMM_SMEM);
    cudaFuncSetAttribute(k_mma_gemm<1,2>, cudaFuncAttributeMaxDynamicSharedMemorySize, GEMM_SMEM);
    cudaFuncSetAttribute(k_mma_gemm<2,2>, cudaFuncAttributeMaxDynamicSharedMemorySize, GEMM_SMEM);
    cudaFuncSetAttribute(k_attn, cudaFuncAttributeMaxDynamicSharedMemorySize, 65536);

    // 1. pos dwconv + residual -> xh (NHWC)
    k_posconv<<<dim3(BB*HH, 2), 256>>>(x, pos_w, pos_b, p_xh);
    // 2. LN1 -> split bf16 y
    k_ln<<<TOK/8, 256>>>(p_xh, ln1_g, ln1_b, p_yh, p_yl);
    // 3. fused weight transpose + split
    k_wsplit_all<<<640, 256>>>(qkv_w, wo_w, mlp_w1, mlp_w2,
                               p_wqh, p_wql, p_woh, p_wol,
                               p_w1h, p_w1l, p_w2h, p_w2l);
    // 4. QKV gemm -> qkv fp32 (3-term: routing depends on it)   [profiled launch]
    k_mma_gemm<0,3><<<dim3(TOK/128, QKVC/64), 256, GEMM_SMEM>>>(
        p_yh, p_yl, p_wqh, p_wql, qkv_b, nullptr, p_qkv, nullptr, nullptr, QKVC, CC);
    // 5. window means
    k_winmean<<<BB*P2, 256>>>(p_qkv, p_qwin, p_kwin);
    // 6. routing top-4
    k_route<<<BB*P2, 64>>>(p_qwin, p_kwin, p_idx);
    // 7. attention -> att fp32 (NHWC)
    k_attn<<<BB*P2, 256, 65536>>>(p_qkv, p_idx, p_att);
    // 8. lepe: att + dwconv5x5(v) -> split bf16
    k_lepe<<<dim3(BB*HH, 4), 256>>>(p_qkv, lepe_w, lepe_b, p_att, p_ath, p_atl);
    // 9. wo gemm with residual (2-term): xh = xh + (att+lepe) @ wo + b
    k_mma_gemm<2,2><<<dim3(TOK/128, CC/64), 256, GEMM_SMEM>>>(
        p_ath, p_atl, p_woh, p_wol, wo_b, p_xh, p_xh, nullptr, nullptr, CC, CC);
    // 10. LN2 -> split bf16 y
    k_ln<<<TOK/8, 256>>>(p_xh, ln2_g, ln2_b, p_yh, p_yl);
    // 11. mlp1 + gelu (2-term) -> split bf16 h1
    k_mma_gemm<1,2><<<dim3(TOK/128, 3*CC/64), 256, GEMM_SMEM>>>(
        p_yh, p_yl, p_w1h, p_w1l, mlp_b1, nullptr, nullptr, p_h1h, p_h1l, 3*CC, CC);
    // 12. mlp2 with residual (2-term): xh = xh + h1 @ w2 + b
    k_mma_gemm<2,2><<<dim3(TOK/128, CC/64), 256, GEMM_SMEM>>>(
        p_h1h, p_h1l, p_w2h, p_w2l, mlp_b2, p_xh, p_xh, nullptr, nullptr, CC, 3*CC);
    // 13. NHWC -> NCHW
    k_tr<<<dim3((HH*WWI)/32, CC/32, BB), dim3(32, 8)>>>(p_xh, out);
}

// round 5
// speedup vs baseline: 1.6422x; 1.6422x over previous
#include <cuda_runtime.h>
#include <cuda_bf16.h>
#include <cstdint>

#define BB 16
#define CC 128
#define HH 56
#define WWI 56
#define TOK (BB*HH*WWI)          // 50176
#define QKC 128
#define QKVC 384
#define NWIN 7
#define WHS 8
#define P2 49
#define W2 64
#define TOPK 4
#define HEADS 4
#define HD 32
#define SCALE 0.08838834764831845f

typedef unsigned long long ull;

// ---------------- scratch (device globals; no allocation) ----------------
__device__ float g_xh [TOK*CC];
__device__ float g_qkv[TOK*QKVC];
__device__ float g_att[TOK*CC];
__device__ float g_qwin[BB*P2*CC];
__device__ float g_kwin[BB*P2*CC];
__device__ int   g_idx [BB*P2*TOPK];
// split-bf16 activations
__device__ __nv_bfloat16 g_yh [TOK*CC],  g_yl [TOK*CC];
__device__ __nv_bfloat16 g_ath[TOK*CC],  g_atl[TOK*CC];
__device__ __nv_bfloat16 g_h1h[TOK*3*CC],g_h1l[TOK*3*CC];
// split-bf16 weights, transposed to [N,K]
__device__ __nv_bfloat16 g_wqh[QKVC*CC], g_wql[QKVC*CC];
__device__ __nv_bfloat16 g_woh[CC*CC],   g_wol[CC*CC];
__device__ __nv_bfloat16 g_w1h[3*CC*CC], g_w1l[3*CC*CC];
__device__ __nv_bfloat16 g_w2h[CC*3*CC], g_w2l[CC*3*CC];

// ---------------- helpers ----------------
__device__ __forceinline__ uint32_t smem_u32(const void* p){
    uint32_t a;
    asm("{ .reg .u64 t; cvta.to.shared.u64 t, %1; cvt.u32.u64 %0, t; }" : "=r"(a) : "l"(p));
    return a;
}
__device__ __forceinline__ void ldm_x4(uint32_t& r0,uint32_t& r1,uint32_t& r2,uint32_t& r3, uint32_t addr){
    asm volatile("ldmatrix.sync.aligned.m8n8.x4.shared.b16 {%0,%1,%2,%3}, [%4];"
        : "=r"(r0),"=r"(r1),"=r"(r2),"=r"(r3) : "r"(addr));
}
__device__ __forceinline__ void ldm_x4_t(uint32_t& r0,uint32_t& r1,uint32_t& r2,uint32_t& r3, uint32_t addr){
    asm volatile("ldmatrix.sync.aligned.m8n8.x4.trans.shared.b16 {%0,%1,%2,%3}, [%4];"
        : "=r"(r0),"=r"(r1),"=r"(r2),"=r"(r3) : "r"(addr));
}
__device__ __forceinline__ void mma_bf16(float* d, const uint32_t* a, const uint32_t* b){
    asm volatile("mma.sync.aligned.m16n8k16.row.col.f32.bf16.bf16.f32 "
        "{%0,%1,%2,%3}, {%4,%5,%6,%7}, {%8,%9}, {%0,%1,%2,%3};"
        : "+f"(d[0]),"+f"(d[1]),"+f"(d[2]),"+f"(d[3])
        : "r"(a[0]),"r"(a[1]),"r"(a[2]),"r"(a[3]), "r"(b[0]),"r"(b[1]));
}
__device__ __forceinline__ uint32_t packbf2(float lo, float hi){
    uint32_t r;
    asm("cvt.rn.bf16x2.f32 %0, %1, %2;" : "=r"(r) : "f"(hi), "f"(lo));
    return r;
}
__device__ __forceinline__ float gelu_exact(float v){
    return 0.5f * v * (1.0f + erff(v * 0.70710678118654752f));
}
__device__ __forceinline__ void split_bf16(float v, __nv_bfloat16& h, __nv_bfloat16& l){
    h = __float2bfloat16(v);
    l = __float2bfloat16(v - __bfloat162float(h));
}

// ---------------- fused weight transpose + split (one launch) ----------------
__global__ __launch_bounds__(256) void k_wsplit_all(
    const float* __restrict__ qkv_w, const float* __restrict__ wo_w,
    const float* __restrict__ mlp_w1, const float* __restrict__ mlp_w2,
    __nv_bfloat16* __restrict__ wqh, __nv_bfloat16* __restrict__ wql,
    __nv_bfloat16* __restrict__ woh, __nv_bfloat16* __restrict__ wol,
    __nv_bfloat16* __restrict__ w1h, __nv_bfloat16* __restrict__ w1l,
    __nv_bfloat16* __restrict__ w2h, __nv_bfloat16* __restrict__ w2l)
{
    int blk = blockIdx.x;
    const float* src; __nv_bfloat16 *dh, *dl; int K, N, base;
    if (blk < 192)      { src = qkv_w;  dh = wqh; dl = wql; K = CC;   N = QKVC; base = 0;   }
    else if (blk < 256) { src = wo_w;   dh = woh; dl = wol; K = CC;   N = CC;   base = 192; }
    else if (blk < 448) { src = mlp_w1; dh = w1h; dl = w1l; K = CC;   N = 3*CC; base = 256; }
    else                { src = mlp_w2; dh = w2h; dl = w2l; K = 3*CC; N = CC;   base = 448; }
    int i = (blk - base) * 256 + threadIdx.x;
    if (i >= N * K) return;
    int n = i / K, k = i - n * K;
    float v = src[(size_t)k * N + n];
    __nv_bfloat16 h, l; split_bf16(v, h, l);
    dh[i] = h; dl[i] = l;
}

// ---------------- kernel 1: x + dwconv3x3(x) -> xh (NHWC) ----------------
__global__ __launch_bounds__(256) void k_posconv(const float* __restrict__ x,
                                                 const float* __restrict__ pw,
                                                 const float* __restrict__ pb,
                                                 float* __restrict__ xh){
    __shared__ __align__(16) float s[3*64*57];
    int bh = blockIdx.x; int b = bh / HH, h = bh % HH;
    int c0 = blockIdx.y * 64;
    int tid = threadIdx.x;
    for (int l = tid; l < 3*64*56; l += 256){
        int row = l / (64*56);
        int rem = l - row*(64*56);
        int c   = rem / 56;
        int wv  = rem - c*56;
        int hr  = h + row - 1;
        float v = 0.f;
        if (hr >= 0 && hr < HH)
            v = x[((size_t)((b*CC + c0 + c)*HH + hr))*WWI + wv];
        s[row*64*57 + c*57 + wv] = v;
    }
    __syncthreads();
    int c = tid & 63;
    float wgt[9];
    #pragma unroll
    for (int t = 0; t < 9; t++) wgt[t] = pw[(c0 + c)*9 + t];
    float bias = pb[c0 + c];
    for (int l = tid; l < 56*64; l += 256){
        int w = l >> 6;
        float acc = bias;
        #pragma unroll
        for (int ky = 0; ky < 3; ky++){
            const float* srow = &s[ky*64*57 + c*57];
            #pragma unroll
            for (int kx = 0; kx < 3; kx++){
                int ww = w + kx - 1;
                if (ww >= 0 && ww < WWI) acc += wgt[ky*3+kx] * srow[ww];
            }
        }
        acc += s[1*64*57 + c*57 + w];   // residual (center x)
        xh[((size_t)((b*HH + h)*WWI + w))*CC + c0 + c] = acc;
    }
}

// ---------------- kernel 2: LayerNorm over C -> split bf16 ----------------
__global__ __launch_bounds__(256) void k_ln(const float* __restrict__ in,
                                            const float* __restrict__ g,
                                            const float* __restrict__ bt,
                                            __nv_bfloat16* __restrict__ oh,
                                            __nv_bfloat16* __restrict__ ol){
    int warp = threadIdx.x >> 5, lane = threadIdx.x & 31;
    int tok = blockIdx.x * 8 + warp;
    const float4* ip = (const float4*)(in + (size_t)tok * CC);
    float4 v = ip[lane];
    float s = v.x + v.y + v.z + v.w;
    float q = v.x*v.x + v.y*v.y + v.z*v.z + v.w*v.w;
    #pragma unroll
    for (int o = 16; o; o >>= 1){
        s += __shfl_xor_sync(0xffffffffu, s, o);
        q += __shfl_xor_sync(0xffffffffu, q, o);
    }
    float m   = s * (1.f/128.f);
    float var = q * (1.f/128.f) - m*m;
    float r   = rsqrtf(var + 1e-6f);
    float4 gg = ((const float4*)g)[lane];
    float4 bb = ((const float4*)bt)[lane];
    float o0 = (v.x - m)*r*gg.x + bb.x;
    float o1 = (v.y - m)*r*gg.y + bb.y;
    float o2 = (v.z - m)*r*gg.z + bb.z;
    float o3 = (v.w - m)*r*gg.w + bb.w;
    __nv_bfloat16 h0,h1,h2,h3,l0,l1,l2,l3;
    split_bf16(o0,h0,l0); split_bf16(o1,h1,l1); split_bf16(o2,h2,l2); split_bf16(o3,h3,l3);
    size_t off = (size_t)tok * CC + lane*4;
    *(__nv_bfloat162*)(oh + off)     = __nv_bfloat162(h0, h1);
    *(__nv_bfloat162*)(oh + off + 2) = __nv_bfloat162(h2, h3);
    *(__nv_bfloat162*)(ol + off)     = __nv_bfloat162(l0, l1);
    *(__nv_bfloat162*)(ol + off + 2) = __nv_bfloat162(l2, l3);
}

// ---------------- HMMA GEMM: C[M,N] = A[M,K] @ W, split-bf16 ----------------
#define ASTR 72   // smem row stride in bf16 (144B: conflict-free ldmatrix)
template<int EPI, int TERMS>
__global__ __launch_bounds__(256) void k_mma_gemm(
    const __nv_bfloat16* __restrict__ Ah, const __nv_bfloat16* __restrict__ Al,
    const __nv_bfloat16* __restrict__ Bh, const __nv_bfloat16* __restrict__ Bl,
    const float* __restrict__ bias, const float* __restrict__ R,
    float* __restrict__ C, __nv_bfloat16* __restrict__ C1, __nv_bfloat16* __restrict__ C2,
    int N, int K)
{
    extern __shared__ __align__(16) __nv_bfloat16 sm[];
    __nv_bfloat16* sAh = sm;                    // 128 x ASTR
    __nv_bfloat16* sAl = sm + 128*ASTR;         // 128 x ASTR
    __nv_bfloat16* sBh = sm + 2*128*ASTR;       // 64 x ASTR
    __nv_bfloat16* sBl = sm + 2*128*ASTR + 64*ASTR;

    int tid = threadIdx.x;
    int warp = tid >> 5, lane = tid & 31;
    int wy = warp >> 1, wx = warp & 1;          // wy: M (0..3), wx: N (0..1)
    int bm = blockIdx.x * 128, bn = blockIdx.y * 64;

    float d[2][4][4];
    #pragma unroll
    for (int mt = 0; mt < 2; mt++)
        #pragma unroll
        for (int nt = 0; nt < 4; nt++)
            #pragma unroll
            for (int i = 0; i < 4; i++) d[mt][nt][i] = 0.f;

    int lr = tid >> 3;          // 0..31
    int lc = (tid & 7) * 8;     // 0..56

    for (int kc = 0; kc < K; kc += 64){
        if (kc) __syncthreads();
        #pragma unroll
        for (int p = 0; p < 4; p++){
            int row = p*32 + lr;
            *(uint4*)&sAh[row*ASTR + lc] = *(const uint4*)(Ah + (size_t)(bm+row)*K + kc + lc);
            *(uint4*)&sAl[row*ASTR + lc] = *(const uint4*)(Al + (size_t)(bm+row)*K + kc + lc);
        }
        #pragma unroll
        for (int p = 0; p < 2; p++){
            int row = p*32 + lr;
            *(uint4*)&sBh[row*ASTR + lc] = *(const uint4*)(Bh + (size_t)(bn+row)*K + kc + lc);
            if (TERMS == 3)
                *(uint4*)&sBl[row*ASTR + lc] = *(const uint4*)(Bl + (size_t)(bn+row)*K + kc + lc);
        }
        __syncthreads();
        #pragma unroll
        for (int ks = 0; ks < 4; ks++){
            uint32_t ah[2][4], al[2][4], bh[4][2], bl[4][2];
            #pragma unroll
            for (int mt = 0; mt < 2; mt++){
                int r = wy*32 + mt*16 + (lane & 15);
                int c = ks*16 + (lane >> 4)*8;
                ldm_x4(ah[mt][0],ah[mt][1],ah[mt][2],ah[mt][3], smem_u32(&sAh[r*ASTR + c]));
                ldm_x4(al[mt][0],al[mt][1],al[mt][2],al[mt][3], smem_u32(&sAl[r*ASTR + c]));
            }
            #pragma unroll
            for (int nn = 0; nn < 2; nn++){
                int g8 = lane >> 3;
                int n = wx*32 + nn*16 + ((g8 >> 1) ? 8 : 0) + (lane & 7);
                int c = ks*16 + (g8 & 1)*8;
                uint32_t r0,r1,r2,r3;
                ldm_x4(r0,r1,r2,r3, smem_u32(&sBh[n*ASTR + c]));
                bh[nn*2+0][0]=r0; bh[nn*2+0][1]=r1; bh[nn*2+1][0]=r2; bh[nn*2+1][1]=r3;
                if (TERMS == 3){
                    ldm_x4(r0,r1,r2,r3, smem_u32(&sBl[n*ASTR + c]));
                    bl[nn*2+0][0]=r0; bl[nn*2+0][1]=r1; bl[nn*2+1][0]=r2; bl[nn*2+1][1]=r3;
                }
            }
            #pragma unroll
            for (int mt = 0; mt < 2; mt++)
                #pragma unroll
                for (int nt = 0; nt < 4; nt++){
                    mma_bf16(d[mt][nt], ah[mt], bh[nt]);       // Ah*Bh
                    mma_bf16(d[mt][nt], al[mt], bh[nt]);       // Al*Bh
                    if (TERMS == 3)
                        mma_bf16(d[mt][nt], ah[mt], bl[nt]);   // Ah*Bl
                }
        }
    }

    int g = lane >> 2, t = lane & 3;
    #pragma unroll
    for (int mt = 0; mt < 2; mt++){
        #pragma unroll
        for (int nt = 0; nt < 4; nt++){
            int c = bn + wx*32 + nt*8 + t*2;
            float b0 = bias[c], b1 = bias[c+1];
            #pragma unroll
            for (int hr = 0; hr < 2; hr++){
                int r = bm + wy*32 + mt*16 + g + hr*8;
                float v0 = d[mt][nt][hr*2+0] + b0;
                float v1 = d[mt][nt][hr*2+1] + b1;
                size_t go = (size_t)r * N + c;
                if (EPI == 0){
                    float2 o; o.x = v0; o.y = v1;
                    *(float2*)(C + go) = o;
                } else if (EPI == 1){
                    v0 = gelu_exact(v0); v1 = gelu_exact(v1);
                    __nv_bfloat16 h0,h1,l0,l1;
                    split_bf16(v0,h0,l0); split_bf16(v1,h1,l1);
                    *(__nv_bfloat162*)(C1 + go) = __nv_bfloat162(h0, h1);
                    *(__nv_bfloat162*)(C2 + go) = __nv_bfloat162(l0, l1);
                } else {
                    float2 rr = *(const float2*)(R + go);
                    float2 o; o.x = v0 + rr.x; o.y = v1 + rr.y;
                    *(float2*)(C + go) = o;
                }
            }
        }
    }
}
#define GEMM_SMEM ((2*128*ASTR + 2*64*ASTR) * 2)

// ---------------- kernel 4: window means of q and k (256 thr) ----------------
__global__ __launch_bounds__(256) void k_winmean(const float* __restrict__ qkv,
                                                 float* __restrict__ qwin,
                                                 float* __restrict__ kwin){
    int bp = blockIdx.x; int b = bp / P2, p = bp - b*P2;
    int tid = threadIdx.x;
    int c = tid & 127, isK = tid >> 7;
    int hb = (p / NWIN) * WHS, wb = (p % NWIN) * WHS;
    const float* src = qkv + (isK ? QKC : 0) + c;
    float s = 0.f;
    #pragma unroll 8
    for (int r = 0; r < W2; r++){
        size_t tok = (size_t)(b*HH + hb + (r >> 3))*WWI + wb + (r & 7);
        s += src[tok*QKVC];
    }
    (isK ? kwin : qwin)[(size_t)bp*CC + c] = s * (1.f/64.f);
}

// ---------------- kernel 5: routing logits + top-4 ----------------
__global__ __launch_bounds__(64) void k_route(const float* __restrict__ qwin,
                                              const float* __restrict__ kwin,
                                              int* __restrict__ idx){
    __shared__ float qr[128];
    __shared__ float lg[49];
    int bp = blockIdx.x; int b = bp / P2;
    int t = threadIdx.x;
    qr[t]      = qwin[(size_t)bp*CC + t];
    qr[t + 64] = qwin[(size_t)bp*CC + 64 + t];
    __syncthreads();
    if (t < P2){
        const float* kr = kwin + (size_t)(b*P2 + t)*CC;
        float s = 0.f;
        #pragma unroll 8
        for (int c = 0; c < CC; c++) s += qr[c] * kr[c];
        lg[t] = s;
    }
    __syncthreads();
    if (t == 0){
        unsigned long long used = 0ull;
        for (int r = 0; r < TOPK; r++){
            float best = -1e30f; int bi = 0;
            for (int j = 0; j < P2; j++)
                if (!((used >> j) & 1ull) && lg[j] > best){ best = lg[j]; bi = j; }
            used |= 1ull << bi;
            idx[bp*TOPK + r] = bi;
        }
    }
}

// ---------------- kernel 6: HMMA flash attention ----------------
// 8 warps: warp = head h (w>>1) x query-half qh (w&1). 64 q x 256 keys per block.
// S = Qh*Kh + Ql*Kh (K single bf16). P*V = Ph*Vh + Ph*Vl (P single bf16, V split).
#define QSTR 136                 // bf16 row stride (272B), conflict-free ldmatrix
#define QSZ  (64*QSTR)
__global__ __launch_bounds__(256) void k_attn(const float* __restrict__ qkv,
                                              const int* __restrict__ idx,
                                              float* __restrict__ op){
    extern __shared__ __align__(16) __nv_bfloat16 sm[];
    __nv_bfloat16* sQh = sm;
    __nv_bfloat16* sQl = sm + QSZ;
    __nv_bfloat16* sKh = sm + 2*QSZ;
    __nv_bfloat16* sVh = sm + 3*QSZ;
    __nv_bfloat16* sVl = sm + 4*QSZ;

    int bp = blockIdx.x; int b = bp / P2, p = bp - b*P2;
    int tid = threadIdx.x;
    int warp = tid >> 5, lane = tid & 31;
    int h = warp >> 1, qh = warp & 1;
    int g = lane >> 2, t4 = lane & 3;
    int ro = lane & 7, grp = lane >> 3;
    int hb = (p / NWIN)*WHS, wb = (p % NWIN)*WHS;

    // stage Q (scaled, split hi/lo)
    #pragma unroll
    for (int i = 0; i < 16; i++){
        int li = i*256 + tid;
        int r = li >> 6, c2 = (li & 63)*2;
        size_t tok = (size_t)(b*HH + hb + (r >> 3))*WWI + wb + (r & 7);
        float2 v = *(const float2*)(qkv + tok*QKVC + c2);
        v.x *= SCALE; v.y *= SCALE;
        __nv_bfloat16 h0,l0,h1,l1;
        split_bf16(v.x,h0,l0); split_bf16(v.y,h1,l1);
        *(__nv_bfloat162*)&sQh[r*QSTR + c2] = __nv_bfloat162(h0,h1);
        *(__nv_bfloat162*)&sQl[r*QSTR + c2] = __nv_bfloat162(l0,l1);
    }
    __syncthreads();

    // Q fragments (persistent)
    uint32_t qah[2][2][4], qal[2][2][4];
    #pragma unroll
    for (int mt = 0; mt < 2; mt++)
        #pragma unroll
        for (int ks = 0; ks < 2; ks++){
            int row = qh*32 + mt*16 + (grp & 1)*8 + ro;
            int col = h*32 + ks*16 + (grp >> 1)*8;
            ldm_x4(qah[mt][ks][0],qah[mt][ks][1],qah[mt][ks][2],qah[mt][ks][3],
                   smem_u32(&sQh[row*QSTR + col]));
            ldm_x4(qal[mt][ks][0],qal[mt][ks][1],qal[mt][ks][2],qal[mt][ks][3],
                   smem_u32(&sQl[row*QSTR + col]));
        }

    float o[2][4][4];
    #pragma unroll
    for (int mt = 0; mt < 2; mt++)
        #pragma unroll
        for (int nt = 0; nt < 4; nt++)
            #pragma unroll
            for (int i = 0; i < 4; i++) o[mt][nt][i] = 0.f;
    float mst[2][2] = {{-1e30f,-1e30f},{-1e30f,-1e30f}};
    float lst[2][2] = {{0.f,0.f},{0.f,0.f}};

    for (int tt = 0; tt < TOPK; tt++){
        int wsel = idx[bp*TOPK + tt];
        int bh2 = (wsel / NWIN)*WHS, bw2 = (wsel % NWIN)*WHS;
        __syncthreads();
        // stage K (hi only) and V (split)
        #pragma unroll
        for (int i = 0; i < 32; i++){
            int li = i*256 + tid;
            int k = li >> 7, c2 = (li & 127)*2;
            size_t tok = (size_t)(b*HH + bh2 + (k >> 3))*WWI + bw2 + (k & 7);
            float2 v = *(const float2*)(qkv + tok*QKVC + QKC + c2);
            if (c2 < 128){
                *(__nv_bfloat162*)&sKh[k*QSTR + c2] =
                    __nv_bfloat162(__float2bfloat16(v.x), __float2bfloat16(v.y));
            } else {
                int cv = c2 - 128;
                __nv_bfloat16 h0,l0,h1,l1;
                split_bf16(v.x,h0,l0); split_bf16(v.y,h1,l1);
                *(__nv_bfloat162*)&sVh[k*QSTR + cv] = __nv_bfloat162(h0,h1);
                *(__nv_bfloat162*)&sVl[k*QSTR + cv] = __nv_bfloat162(l0,l1);
            }
        }
        __syncthreads();

        // S = Q . K^T   (32q x 64k per warp)
        float s[2][8][4];
        #pragma unroll
        for (int mt = 0; mt < 2; mt++)
            #pragma unroll
            for (int nt = 0; nt < 8; nt++)
                #pragma unroll
                for (int i = 0; i < 4; i++) s[mt][nt][i] = 0.f;
        #pragma unroll
        for (int ks = 0; ks < 2; ks++){
            uint32_t kb[8][2];
            int col = h*32 + ks*16 + (grp & 1)*8;
            #pragma unroll
            for (int j = 0; j < 4; j++){
                int row = j*16 + (grp >> 1)*8 + ro;
                uint32_t r0,r1,r2,r3;
                ldm_x4(r0,r1,r2,r3, smem_u32(&sKh[row*QSTR + col]));
                kb[2*j][0]=r0; kb[2*j][1]=r1; kb[2*j+1][0]=r2; kb[2*j+1][1]=r3;
            }
            #pragma unroll
            for (int mt = 0; mt < 2; mt++)
                #pragma unroll
                for (int nt = 0; nt < 8; nt++){
                    mma_bf16(s[mt][nt], qah[mt][ks], kb[nt]);
                    mma_bf16(s[mt][nt], qal[mt][ks], kb[nt]);
                }
        }

        // online softmax on fragments; pack P as A-operand
        uint32_t pa[2][4][4];
        #pragma unroll
        for (int mt = 0; mt < 2; mt++){
            float r0 = -1e30f, r1 = -1e30f;
            #pragma unroll
            for (int nt = 0; nt < 8; nt++){
                r0 = fmaxf(r0, fmaxf(s[mt][nt][0], s[mt][nt][1]));
                r1 = fmaxf(r1, fmaxf(s[mt][nt][2], s[mt][nt][3]));
            }
            r0 = fmaxf(r0, __shfl_xor_sync(0xffffffffu, r0, 1));
            r0 = fmaxf(r0, __shfl_xor_sync(0xffffffffu, r0, 2));
            r1 = fmaxf(r1, __shfl_xor_sync(0xffffffffu, r1, 1));
            r1 = fmaxf(r1, __shfl_xor_sync(0xffffffffu, r1, 2));
            float mn0 = fmaxf(mst[mt][0], r0), mn1 = fmaxf(mst[mt][1], r1);
            float c0 = __expf(mst[mt][0] - mn0), c1 = __expf(mst[mt][1] - mn1);
            mst[mt][0] = mn0; mst[mt][1] = mn1;
            float ls0 = 0.f, ls1 = 0.f;
            #pragma unroll
            for (int nt = 0; nt < 8; nt++){
                float e0 = __expf(s[mt][nt][0] - mn0);
                float e1 = __expf(s[mt][nt][1] - mn0);
                float e2 = __expf(s[mt][nt][2] - mn1);
                float e3 = __expf(s[mt][nt][3] - mn1);
                ls0 += e0 + e1; ls1 += e2 + e3;
                s[mt][nt][0] = e0; s[mt][nt][1] = e1;
                s[mt][nt][2] = e2; s[mt][nt][3] = e3;
            }
            ls0 += __shfl_xor_sync(0xffffffffu, ls0, 1);
            ls0 += __shfl_xor_sync(0xffffffffu, ls0, 2);
            ls1 += __shfl_xor_sync(0xffffffffu, ls1, 1);
            ls1 += __shfl_xor_sync(0xffffffffu, ls1, 2);
            lst[mt][0] = lst[mt][0]*c0 + ls0;
            lst[mt][1] = lst[mt][1]*c1 + ls1;
            #pragma unroll
            for (int nt = 0; nt < 4; nt++){
                o[mt][nt][0] *= c0; o[mt][nt][1] *= c0;
                o[mt][nt][2] *= c1; o[mt][nt][3] *= c1;
            }
            #pragma unroll
            for (int k2 = 0; k2 < 4; k2++){
                pa[mt][k2][0] = packbf2(s[mt][2*k2][0],   s[mt][2*k2][1]);
                pa[mt][k2][1] = packbf2(s[mt][2*k2][2],   s[mt][2*k2][3]);
                pa[mt][k2][2] = packbf2(s[mt][2*k2+1][0], s[mt][2*k2+1][1]);
                pa[mt][k2][3] = packbf2(s[mt][2*k2+1][2], s[mt][2*k2+1][3]);
            }
        }

        // O += P . V
        #pragma unroll
        for (int k2 = 0; k2 < 4; k2++){
            uint32_t vbh[4][2], vbl[4][2];
            int row = k2*16 + (grp & 1)*8 + ro;
            #pragma unroll
            for (int np = 0; np < 2; np++){
                int col = h*32 + np*16 + (grp >> 1)*8;
                uint32_t r0,r1,r2,r3;
                ldm_x4_t(r0,r1,r2,r3, smem_u32(&sVh[row*QSTR + col]));
                vbh[2*np][0]=r0; vbh[2*np][1]=r1; vbh[2*np+1][0]=r2; vbh[2*np+1][1]=r3;
                ldm_x4_t(r0,r1,r2,r3, smem_u32(&sVl[row*QSTR + col]));
                vbl[2*np][0]=r0; vbl[2*np][1]=r1; vbl[2*np+1][0]=r2; vbl[2*np+1][1]=r3;
            }
            #pragma unroll
            for (int mt = 0; mt < 2; mt++)
                #pragma unroll
                for (int nt = 0; nt < 4; nt++){
                    mma_bf16(o[mt][nt], pa[mt][k2], vbh[nt]);
                    mma_bf16(o[mt][nt], pa[mt][k2], vbl[nt]);
                }
        }
    }

    // normalize + write
    #pragma unroll
    for (int mt = 0; mt < 2; mt++){
        float inv0 = 1.f / lst[mt][0], inv1 = 1.f / lst[mt][1];
        int r0 = qh*32 + mt*16 + g, r1 = r0 + 8;
        size_t tok0 = (size_t)(b*HH + hb + (r0 >> 3))*WWI + wb + (r0 & 7);
        size_t tok1 = (size_t)(b*HH + hb + (r1 >> 3))*WWI + wb + (r1 & 7);
        #pragma unroll
        for (int nt = 0; nt < 4; nt++){
            int col = h*32 + nt*8 + t4*2;
            float2 v0; v0.x = o[mt][nt][0]*inv0; v0.y = o[mt][nt][1]*inv0;
            float2 v1; v1.x = o[mt][nt][2]*inv1; v1.y = o[mt][nt][3]*inv1;
            *(float2*)(op + tok0*CC + col) = v0;
            *(float2*)(op + tok1*CC + col) = v1;
        }
    }
}
#define ATTN_SMEM (5*QSZ*2)

// ---------------- kernel 7: LEPE 5x5 dwconv on v, add att, write split bf16 ----------------
__global__ __launch_bounds__(256) void k_lepe(const float* __restrict__ qkv,
                                              const float* __restrict__ lw,
                                              const float* __restrict__ lb,
                                              const float* __restrict__ att,
                                              __nv_bfloat16* __restrict__ oh,
                                              __nv_bfloat16* __restrict__ ol){
    __shared__ __align__(16) float s[5*32*57];
    int bh = blockIdx.x; int b = bh / HH, h = bh % HH;
    int c0 = blockIdx.y * 32;
    int tid = threadIdx.x;
    for (int l = tid; l < 5*32*56; l += 256){
        int row = l / (32*56);
        int rem = l - row*(32*56);
        int wv  = rem >> 5;
        int c   = rem & 31;
        int hr  = h + row - 2;
        float v = 0.f;
        if (hr >= 0 && hr < HH)
            v = qkv[((size_t)((b*HH + hr)*WWI + wv))*QKVC + 2*QKC + c0 + c];
        s[row*32*57 + c*57 + wv] = v;
    }
    __syncthreads();
    int c = tid & 31;
    float wg[25];
    #pragma unroll
    for (int t = 0; t < 25; t++) wg[t] = lw[(c0 + c)*25 + t];
    float bias = lb[c0 + c];
    for (int l = tid; l < 56*32; l += 256){
        int w = l >> 5;
        float acc = bias;
        #pragma unroll
        for (int ky = 0; ky < 5; ky++){
            const float* srow = &s[ky*32*57 + c*57];
            #pragma unroll
            for (int kx = 0; kx < 5; kx++){
                int ww = w + kx - 2;
                if (ww >= 0 && ww < WWI) acc += wg[ky*5+kx] * srow[ww];
            }
        }
        size_t go = ((size_t)((b*HH + h)*WWI + w))*CC + c0 + c;
        float v = att[go] + acc;
        __nv_bfloat16 hh, ll; split_bf16(v, hh, ll);
        oh[go] = hh; ol[go] = ll;
    }
}

// ---------------- kernel 8: NHWC -> NCHW ----------------
__global__ void k_tr(const float* __restrict__ in, float* __restrict__ out){
    __shared__ float t[32][33];
    int b = blockIdx.z, c0 = blockIdx.y*32, p0 = blockIdx.x*32;
    int tx = threadIdx.x, ty = threadIdx.y;
    #pragma unroll
    for (int u = 0; u < 4; u++)
        t[ty + u*8][tx] = in[((size_t)(b*(HH*WWI) + p0 + ty + u*8))*CC + c0 + tx];
    __syncthreads();
    #pragma unroll
    for (int u = 0; u < 4; u++)
        out[((size_t)(b*CC + c0 + ty + u*8))*(HH*WWI) + p0 + tx] = t[tx][ty + u*8];
}

// ---------------- launcher ----------------
extern "C" void kernel_launch(void* const* d_in, const int* in_sizes, int n_in,
                              void* d_out, int out_size){
    const float* x      = (const float*)d_in[0];
    const float* pos_w  = (const float*)d_in[1];
    const float* pos_b  = (const float*)d_in[2];
    const float* ln1_g  = (const float*)d_in[3];
    const float* ln1_b  = (const float*)d_in[4];
    const float* qkv_w  = (const float*)d_in[5];
    const float* qkv_b  = (const float*)d_in[6];
    const float* lepe_w = (const float*)d_in[7];
    const float* lepe_b = (const float*)d_in[8];
    const float* wo_w   = (const float*)d_in[9];
    const float* wo_b   = (const float*)d_in[10];
    const float* ln2_g  = (const float*)d_in[11];
    const float* ln2_b  = (const float*)d_in[12];
    const float* mlp_w1 = (const float*)d_in[13];
    const float* mlp_b1 = (const float*)d_in[14];
    const float* mlp_w2 = (const float*)d_in[15];
    const float* mlp_b2 = (const float*)d_in[16];
    float* out = (float*)d_out;

    float *p_xh, *p_qkv, *p_att, *p_qwin, *p_kwin;
    int *p_idx;
    __nv_bfloat16 *p_yh, *p_yl, *p_ath, *p_atl, *p_h1h, *p_h1l;
    __nv_bfloat16 *p_wqh, *p_wql, *p_woh, *p_wol, *p_w1h, *p_w1l, *p_w2h, *p_w2l;
    cudaGetSymbolAddress((void**)&p_xh,  g_xh);
    cudaGetSymbolAddress((void**)&p_qkv, g_qkv);
    cudaGetSymbolAddress((void**)&p_att, g_att);
    cudaGetSymbolAddress((void**)&p_qwin,g_qwin);
    cudaGetSymbolAddress((void**)&p_kwin,g_kwin);
    cudaGetSymbolAddress((void**)&p_idx, g_idx);
    cudaGetSymbolAddress((void**)&p_yh,  g_yh);
    cudaGetSymbolAddress((void**)&p_yl,  g_yl);
    cudaGetSymbolAddress((void**)&p_ath, g_ath);
    cudaGetSymbolAddress((void**)&p_atl, g_atl);
    cudaGetSymbolAddress((void**)&p_h1h, g_h1h);
    cudaGetSymbolAddress((void**)&p_h1l, g_h1l);
    cudaGetSymbolAddress((void**)&p_wqh, g_wqh);
    cudaGetSymbolAddress((void**)&p_wql, g_wql);
    cudaGetSymbolAddress((void**)&p_woh, g_woh);
    cudaGetSymbolAddress((void**)&p_wol, g_wol);
    cudaGetSymbolAddress((void**)&p_w1h, g_w1h);
    cudaGetSymbolAddress((void**)&p_w1l, g_w1l);
    cudaGetSymbolAddress((void**)&p_w2h, g_w2h);
    cudaGetSymbolAddress((void**)&p_w2l, g_w2l);

    cudaFuncSetAttribute(k_mma_gemm<0,3>, cudaFuncAttributeMaxDynamicSharedMemorySize, GEMM_SMEM);
    cudaFuncSetAttribute(k_mma_gemm<1,2>, cudaFuncAttributeMaxDynamicSharedMemorySize, GEMM_SMEM);
    cudaFuncSetAttribute(k_mma_gemm<2,2>, cudaFuncAttributeMaxDynamicSharedMemorySize, GEMM_SMEM);
    cudaFuncSetAttribute(k_attn, cudaFuncAttributeMaxDynamicSharedMemorySize, ATTN_SMEM);

    // 1. pos dwconv + residual -> xh (NHWC)
    k_posconv<<<dim3(BB*HH, 2), 256>>>(x, pos_w, pos_b, p_xh);
    // 2. LN1 -> split bf16 y
    k_ln<<<TOK/8, 256>>>(p_xh, ln1_g, ln1_b, p_yh, p_yl);
    // 3. fused weight transpose + split
    k_wsplit_all<<<640, 256>>>(qkv_w, wo_w, mlp_w1, mlp_w2,
                               p_wqh, p_wql, p_woh, p_wol,
                               p_w1h, p_w1l, p_w2h, p_w2l);
    // 4. QKV gemm -> qkv fp32 (3-term)   [profiled launch]
    k_mma_gemm<0,3><<<dim3(TOK/128, QKVC/64), 256, GEMM_SMEM>>>(
        p_yh, p_yl, p_wqh, p_wql, qkv_b, nullptr, p_qkv, nullptr, nullptr, QKVC, CC);
    // 5. window means
    k_winmean<<<BB*P2, 256>>>(p_qkv, p_qwin, p_kwin);
    // 6. routing top-4
    k_route<<<BB*P2, 64>>>(p_qwin, p_kwin, p_idx);
    // 7. HMMA attention -> att fp32 (NHWC)
    k_attn<<<BB*P2, 256, ATTN_SMEM>>>(p_qkv, p_idx, p_att);
    // 8. lepe: att + dwconv5x5(v) -> split bf16
    k_lepe<<<dim3(BB*HH, 4), 256>>>(p_qkv, lepe_w, lepe_b, p_att, p_ath, p_atl);
    // 9. wo gemm with residual (2-term): xh = xh + (att+lepe) @ wo + b
    k_mma_gemm<2,2><<<dim3(TOK/128, CC/64), 256, GEMM_SMEM>>>(
        p_ath, p_atl, p_woh, p_wol, wo_b, p_xh, p_xh, nullptr, nullptr, CC, CC);
    // 10. LN2 -> split bf16 y
    k_ln<<<TOK/8, 256>>>(p_xh, ln2_g, ln2_b, p_yh, p_yl);
    // 11. mlp1 + gelu (2-term) -> split bf16 h1
    k_mma_gemm<1,2><<<dim3(TOK/128, 3*CC/64), 256, GEMM_SMEM>>>(
        p_yh, p_yl, p_w1h, p_w1l, mlp_b1, nullptr, nullptr, p_h1h, p_h1l, 3*CC, CC);
    // 12. mlp2 with residual (2-term): xh = xh + h1 @ w2 + b
    k_mma_gemm<2,2><<<dim3(TOK/128, CC/64), 256, GEMM_SMEM>>>(
        p_h1h, p_h1l, p_w2h, p_w2l, mlp_b2, p_xh, p_xh, nullptr, nullptr, CC, 3*CC);
    // 13. NHWC -> NCHW
    k_tr<<<dim3((HH*WWI)/32, CC/32, BB), dim3(32, 8)>>>(p_xh, out);
}